// round 5
// baseline (speedup 1.0000x reference)
#include <cuda_runtime.h>
#include <cstdint>

// Problem constants (fixed shapes for this problem instance)
#define NN   50000
#define EE   800000
#define LM   1024
#define HH   128
#define OUTC 64

// ---------------- scratch (static __device__, no allocation) ----------------
__device__ float g_h1 [(size_t)NN * LM];    // layer-0 output (relu'd)   204.8 MB
__device__ float g_hp1[(size_t)NN * HH];    // h1 @ W1                    25.6 MB
__device__ float g_h2 [(size_t)NN * HH];    // conv1 output (relu'd)      25.6 MB
__device__ float g_hp3[(size_t)NN * OUTC];  // h2 @ W3                    12.8 MB
__device__ float g_deg [NN];
__device__ float g_dis [NN];
__device__ int   g_cnt [NN];
__device__ int   g_rowptr[NN + 1];
__device__ int   g_csr_src [EE];
__device__ float g_csr_coef[EE];
__device__ int   g_is64;                    // edge_index dtype flag

// compile-time buffer selectors (avoids cudaGetSymbolAddress on host)
__device__ __forceinline__ float* sel_buf(int SEL, float* p) {
    switch (SEL) {
        case 1: return g_h1;
        case 2: return g_hp1;
        case 3: return g_h2;
        case 4: return g_hp3;
        default: return p;
    }
}

// edge index fetch honoring detected dtype
__device__ __forceinline__ int edge_at(const void* ei, long long idx) {
    if (g_is64) return (int)((const long long*)ei)[idx];
    return ((const int*)ei)[idx];
}

// ---------------- dtype detection ----------------
// int64 indices < 2^32 have zero high words at every odd 32-bit position.
// 32 consecutive random int32 node ids all being zero is impossible in practice.
__global__ void k_detect(const unsigned int* __restrict__ w) {
    if (threadIdx.x == 0 && blockIdx.x == 0) {
        int is64 = 1;
        for (int i = 1; i < 64; i += 2)
            if (w[i] != 0u) { is64 = 0; break; }
        g_is64 = is64;
    }
}

// ---------------- graph preprocessing ----------------
__global__ void k_init(int n) {
    int i = blockIdx.x * blockDim.x + threadIdx.x;
    if (i < n) { g_deg[i] = 1.0f; g_cnt[i] = 0; }   // self-loop weight 1
}

__global__ void k_count(const void* __restrict__ ei,
                        const float* __restrict__ ew, int e_) {
    int e = blockIdx.x * blockDim.x + threadIdx.x;
    if (e >= e_) return;
    int d = edge_at(ei, (long long)e_ + e);
    atomicAdd(&g_deg[d], ew[e]);
    atomicAdd(&g_cnt[d], 1);
}

// single block, 1024 threads: exclusive scan of cnt -> rowptr, dis=rsqrt(deg), reset cnt
__global__ void k_scan(int n, int e_) {
    __shared__ int warp_sums[32];
    int tid = threadIdx.x;
    const int CH = (n + 1023) / 1024;
    int start = tid * CH;
    int local = 0;
    for (int i = 0; i < CH; i++) {
        int idx = start + i;
        if (idx < n) local += g_cnt[idx];
    }
    int v = local;
    #pragma unroll
    for (int o = 1; o < 32; o <<= 1) {
        int nb = __shfl_up_sync(0xffffffffu, v, o);
        if ((tid & 31) >= o) v += nb;
    }
    if ((tid & 31) == 31) warp_sums[tid >> 5] = v;
    __syncthreads();
    if (tid < 32) {
        int w = warp_sums[tid];
        #pragma unroll
        for (int o = 1; o < 32; o <<= 1) {
            int nb = __shfl_up_sync(0xffffffffu, w, o);
            if (tid >= o) w += nb;
        }
        warp_sums[tid] = w;
    }
    __syncthreads();
    int excl = v - local + ((tid >= 32) ? warp_sums[(tid >> 5) - 1] : 0);
    int run = excl;
    for (int i = 0; i < CH; i++) {
        int idx = start + i;
        if (idx < n) {
            g_rowptr[idx] = run;
            run += g_cnt[idx];
            g_cnt[idx] = 0;          // reuse as fill cursor
            g_dis[idx] = rsqrtf(g_deg[idx]);
        }
    }
    if (tid == 0) g_rowptr[n] = e_;
}

__global__ void k_fill(const void* __restrict__ ei,
                       const float* __restrict__ ew, int e_) {
    int e = blockIdx.x * blockDim.x + threadIdx.x;
    if (e >= e_) return;
    int s = edge_at(ei, e);
    int d = edge_at(ei, (long long)e_ + e);
    int p = g_rowptr[d] + atomicAdd(&g_cnt[d], 1);
    g_csr_src[p]  = s;
    g_csr_coef[p] = g_dis[s] * ew[e] * g_dis[d];
}

// ---------------- tiled fp32 GEMM ----------------
// C[M,N] = A[M,K] @ B[K,N]   (+ optional fused layer-0 epilogue, EPI=1)
// ASEL/DSEL pick scratch buffers at compile time (0 = use pointer param).
template <int BM, int BN, int BK, int TM, int TN, int EPI, int ASEL, int DSEL>
__global__ __launch_bounds__((BM / TM) * (BN / TN))
void k_gemm(const float* __restrict__ Ap, const float* __restrict__ B,
            float* __restrict__ Cp, int M, int N, int K,
            const float* __restrict__ bias,
            const float* __restrict__ cvec, const float* __restrict__ Wc,
            const float* __restrict__ xvec, const float* __restrict__ Wa) {
    const float* __restrict__ A = sel_buf(ASEL, (float*)Ap);
    float* __restrict__ C = sel_buf(DSEL, Cp);

    constexpr int THREADS = (BM / TM) * (BN / TN);
    __shared__ float As[BK][BM];
    __shared__ float Bs[BK][BN];

    const int block_row = blockIdx.y * BM;
    const int block_col = blockIdx.x * BN;
    const int tid  = threadIdx.x;
    const int tcol = tid % (BN / TN);
    const int trow = tid / (BN / TN);

    float acc[TM][TN];
    #pragma unroll
    for (int i = 0; i < TM; i++)
        #pragma unroll
        for (int j = 0; j < TN; j++) acc[i][j] = 0.0f;

    for (int k0 = 0; k0 < K; k0 += BK) {
        // A tile: BM x BK, transposed into As[BK][BM]
        #pragma unroll
        for (int i = tid; i < BM * BK / 4; i += THREADS) {
            int r  = i / (BK / 4);
            int c4 = i % (BK / 4);
            int grow = block_row + r;
            float4 v = (grow < M)
                ? *(const float4*)&A[(size_t)grow * K + k0 + c4 * 4]
                : make_float4(0.f, 0.f, 0.f, 0.f);
            As[c4 * 4 + 0][r] = v.x;
            As[c4 * 4 + 1][r] = v.y;
            As[c4 * 4 + 2][r] = v.z;
            As[c4 * 4 + 3][r] = v.w;
        }
        // B tile: BK x BN
        #pragma unroll
        for (int i = tid; i < BK * BN / 4; i += THREADS) {
            int r  = i / (BN / 4);
            int c4 = i % (BN / 4);
            *(float4*)&Bs[r][c4 * 4] =
                *(const float4*)&B[(size_t)(k0 + r) * N + block_col + c4 * 4];
        }
        __syncthreads();

        #pragma unroll
        for (int k = 0; k < BK; k++) {
            float a[TM], b[TN];
            #pragma unroll
            for (int i = 0; i < TM; i++) a[i] = As[k][trow * TM + i];
            #pragma unroll
            for (int j = 0; j < TN; j++) b[j] = Bs[k][tcol * TN + j];
            #pragma unroll
            for (int i = 0; i < TM; i++)
                #pragma unroll
                for (int j = 0; j < TN; j++)
                    acc[i][j] = fmaf(a[i], b[j], acc[i][j]);
        }
        __syncthreads();
    }

    #pragma unroll
    for (int i = 0; i < TM; i++) {
        int grow = block_row + trow * TM + i;
        if (grow >= M) continue;
        float cv = 0.f, xv = 0.f;
        if (EPI == 1) { cv = cvec[grow]; xv = xvec[grow]; }
        #pragma unroll
        for (int j = 0; j < TN; j++) {
            int gcol = block_col + tcol * TN + j;
            float v = acc[i][j];
            if (EPI == 1) {
                v += bias[gcol] + cv * Wc[gcol] + xv * Wa[gcol];
                v = fmaxf(v, 0.f);
            }
            C[(size_t)grow * N + gcol] = v;
        }
    }
}

// ---------------- GCN aggregation (CSR gather, warp per node) ----------------
// out[d] = bias + sum_{e in in(d)} coef_e * hp[src_e]  +  (dis[d]^2) * hp[d]
template <int F, bool RELU, int HPSEL, int OSEL>
__global__ void k_agg(const float* __restrict__ bias, float* __restrict__ outp, int n) {
    const float* __restrict__ hp = sel_buf(HPSEL, nullptr);
    float* __restrict__ out = sel_buf(OSEL, outp);

    int warp = (blockIdx.x * blockDim.x + threadIdx.x) >> 5;
    int lane = threadIdx.x & 31;
    if (warp >= n) return;
    const int node = warp;
    constexpr int V = F / 32;           // 4 (F=128) or 2 (F=64)
    float acc[V];

    float selfc = g_dis[node] * g_dis[node];
    const float* hrow = hp + (size_t)node * F + lane * V;
    #pragma unroll
    for (int j = 0; j < V; j++) acc[j] = selfc * hrow[j];

    int beg = g_rowptr[node];
    int end = g_rowptr[node + 1];
    for (int e = beg; e < end; e++) {
        int   s  = g_csr_src[e];
        float cf = g_csr_coef[e];
        const float* srow = hp + (size_t)s * F + lane * V;
        if (V == 4) {
            float4 v = *(const float4*)srow;
            acc[0] = fmaf(cf, v.x, acc[0]);
            acc[1] = fmaf(cf, v.y, acc[1]);
            acc[2] = fmaf(cf, v.z, acc[2]);
            acc[3] = fmaf(cf, v.w, acc[3]);
        } else {
            float2 v = *(const float2*)srow;
            acc[0] = fmaf(cf, v.x, acc[0]);
            acc[1] = fmaf(cf, v.y, acc[1]);
        }
    }
    #pragma unroll
    for (int j = 0; j < V; j++) {
        float v = acc[j] + bias[lane * V + j];
        if (RELU) v = fmaxf(v, 0.f);
        out[(size_t)node * F + lane * V + j] = v;
    }
}

// ---------------- launch ----------------
extern "C" void kernel_launch(void* const* d_in, const int* in_sizes, int n_in,
                              void* d_out, int out_size) {
    const float* x    = (const float*)d_in[0];      // [N]
    const float* xout = (const float*)d_in[1];      // [N, LM]
    const float* c    = (const float*)d_in[2];      // [N]
    const void*  ei   = d_in[3];                    // [2, E] int32 or int64
    const float* ew   = (const float*)d_in[4];      // [E]
    const float* Wa   = (const float*)d_in[5];      // [1, LM]
    const float* Wc   = (const float*)d_in[6];      // [1, LM]
    const float* Wl   = (const float*)d_in[7];      // [LM, LM]
    const float* bl   = (const float*)d_in[8];      // [LM]
    const float* W1   = (const float*)d_in[9];      // [LM, H]
    const float* b1   = (const float*)d_in[10];     // [H]
    const float* W3   = (const float*)d_in[11];     // [H, OUT]
    const float* b3   = (const float*)d_in[12];     // [OUT]
    float* out = (float*)d_out;

    const int n = in_sizes[0];
    const int e = in_sizes[3] / 2;

    // --- dtype detection + graph preprocessing ---
    k_detect<<<1, 32>>>((const unsigned int*)ei);
    k_init  <<<(n + 255) / 256, 256>>>(n);
    k_count <<<(e + 255) / 256, 256>>>(ei, ew, e);
    k_scan  <<<1, 1024>>>(n, e);
    k_fill  <<<(e + 255) / 256, 256>>>(ei, ew, e);

    // --- layer 0: g_h1 = relu(xout @ Wl + bl + c*Wc + x*Wa)   [N, LM] ---
    {
        dim3 grid(LM / 128, (n + 127) / 128);
        k_gemm<128, 128, 16, 8, 8, 1, 0, 1><<<grid, 256>>>(
            xout, Wl, nullptr, n, LM, LM, bl, c, Wc, x, Wa);
    }
    // --- conv1 projection: g_hp1 = g_h1 @ W1   [N, H] ---
    {
        dim3 grid(HH / 128, (n + 127) / 128);
        k_gemm<128, 128, 16, 8, 8, 0, 1, 2><<<grid, 256>>>(
            nullptr, W1, nullptr, n, HH, LM, nullptr, nullptr, nullptr, nullptr, nullptr);
    }
    // --- conv1 aggregation + bias + relu:  g_h2 [N, H] ---
    k_agg<HH, true, 2, 3><<<(n * 32 + 255) / 256, 256>>>(b1, nullptr, n);

    // --- conv3 projection: g_hp3 = g_h2 @ W3   [N, OUT] ---
    {
        dim3 grid(OUTC / 64, (n + 127) / 128);
        k_gemm<128, 64, 16, 8, 4, 0, 3, 4><<<grid, 256>>>(
            nullptr, W3, nullptr, n, OUTC, HH, nullptr, nullptr, nullptr, nullptr, nullptr);
    }
    // --- conv3 aggregation + bias:  out [N, OUT] ---
    k_agg<OUTC, false, 4, 0><<<(n * 32 + 255) / 256, 256>>>(b3, out, n);
}

// round 7
// speedup vs baseline: 2.3224x; 2.3224x over previous
#include <cuda_runtime.h>
#include <cuda_bf16.h>
#include <cstdint>

// Problem constants (fixed shapes for this problem instance)
#define NN   50000
#define EE   800000
#define LM   1024
#define HH   128
#define OUTC 64

// ---------------- scratch (static __device__, no allocation) ----------------
__device__ __nv_bfloat16 g_xh [(size_t)NN * LM];   // xout split hi
__device__ __nv_bfloat16 g_xl [(size_t)NN * LM];   // xout split lo
__device__ __nv_bfloat16 g_h1h[(size_t)NN * LM];   // h1 split hi
__device__ __nv_bfloat16 g_h1l[(size_t)NN * LM];   // h1 split lo
__device__ __nv_bfloat16 g_wth [(size_t)LM * LM];  // Wl^T hi   [1024,1024]
__device__ __nv_bfloat16 g_wtl [(size_t)LM * LM];  // Wl^T lo
__device__ __nv_bfloat16 g_w1th[(size_t)HH * LM];  // W1^T hi   [128,1024]
__device__ __nv_bfloat16 g_w1tl[(size_t)HH * LM];  // W1^T lo
__device__ float g_hp1[(size_t)NN * HH];           // h1 @ W1
__device__ float g_h2 [(size_t)NN * HH];           // conv1 output (relu'd)
__device__ float g_hp3[(size_t)NN * OUTC];         // h2 @ W3
__device__ float g_deg [NN];
__device__ float g_dis [NN];
__device__ int   g_cnt [NN];
__device__ int   g_rowptr[NN + 1];
__device__ int   g_csr_src [EE];
__device__ float g_csr_coef[EE];
__device__ int   g_is64;

// ---------------- portable PTX helpers (sm_80+, compile for compute_103) ----
__device__ __forceinline__ uint32_t smem_to_u32(const void* p) {
    uint32_t a;
    asm("{ .reg .u64 t; cvta.to.shared.u64 t, %1; cvt.u32.u64 %0, t; }" : "=r"(a) : "l"(p));
    return a;
}
#define CP_ASYNC16(saddr, gaddr, sz) \
    asm volatile("cp.async.cg.shared.global [%0], [%1], 16, %2;" \
        :: "r"(saddr), "l"(gaddr), "r"(sz))
#define CP_COMMIT() asm volatile("cp.async.commit_group;" ::: "memory")
#define CP_WAIT(n)  asm volatile("cp.async.wait_group %0;" :: "n"(n) : "memory")
#define LDSM_X4(R, ADDR) \
    asm volatile("ldmatrix.sync.aligned.m8n8.x4.shared.b16 {%0,%1,%2,%3}, [%4];" \
        : "=r"((R)[0]), "=r"((R)[1]), "=r"((R)[2]), "=r"((R)[3]) : "r"(ADDR))

__device__ __forceinline__ void mma_bf16(float* d, const uint32_t* a,
                                         uint32_t b0, uint32_t b1) {
    asm volatile(
        "mma.sync.aligned.m16n8k16.row.col.f32.bf16.bf16.f32 "
        "{%0,%1,%2,%3}, {%4,%5,%6,%7}, {%8,%9}, {%0,%1,%2,%3};"
        : "+f"(d[0]), "+f"(d[1]), "+f"(d[2]), "+f"(d[3])
        : "r"(a[0]), "r"(a[1]), "r"(a[2]), "r"(a[3]), "r"(b0), "r"(b1));
}

// ---------------- buffer selectors (avoid host symbol lookups) ----------------
__device__ __forceinline__ float* sel_buf(int SEL, float* p) {
    switch (SEL) {
        case 2: return g_hp1;
        case 3: return g_h2;
        case 4: return g_hp3;
        default: return p;
    }
}
__device__ __forceinline__ const __nv_bfloat16* sel_a(int SEL, int lo) {
    if (SEL == 1) return lo ? g_xl  : g_xh;
    else          return lo ? g_h1l : g_h1h;
}
__device__ __forceinline__ const __nv_bfloat16* sel_b(int SEL, int lo) {
    if (SEL == 1) return lo ? g_wtl  : g_wth;
    else          return lo ? g_w1tl : g_w1th;
}

// edge index fetch honoring detected dtype
__device__ __forceinline__ int edge_at(const void* ei, long long idx) {
    if (g_is64) return (int)((const long long*)ei)[idx];
    return ((const int*)ei)[idx];
}

// ---------------- dtype detection ----------------
__global__ void k_detect(const unsigned int* __restrict__ w) {
    if (threadIdx.x == 0 && blockIdx.x == 0) {
        int is64 = 1;
        for (int i = 1; i < 64; i += 2)
            if (w[i] != 0u) { is64 = 0; break; }
        g_is64 = is64;
    }
}

// ---------------- graph preprocessing ----------------
__global__ void k_init(int n) {
    int i = blockIdx.x * blockDim.x + threadIdx.x;
    if (i < n) { g_deg[i] = 1.0f; g_cnt[i] = 0; }
}

__global__ void k_count(const void* __restrict__ ei, const float* __restrict__ ew, int e_) {
    int e = blockIdx.x * blockDim.x + threadIdx.x;
    if (e >= e_) return;
    int d = edge_at(ei, (long long)e_ + e);
    atomicAdd(&g_deg[d], ew[e]);
    atomicAdd(&g_cnt[d], 1);
}

// single block, 1024 threads, coalesced tile-wise scan
__global__ void k_scan(int n, int e_) {
    __shared__ int wsum[32];
    __shared__ int s_carry;
    int tid = threadIdx.x;
    if (tid == 0) s_carry = 0;
    __syncthreads();
    for (int base = 0; base < n; base += 1024) {
        int idx = base + tid;
        int v = (idx < n) ? g_cnt[idx] : 0;
        int inc = v;
        #pragma unroll
        for (int o = 1; o < 32; o <<= 1) {
            int nb = __shfl_up_sync(0xffffffffu, inc, o);
            if ((tid & 31) >= o) inc += nb;
        }
        if ((tid & 31) == 31) wsum[tid >> 5] = inc;
        __syncthreads();
        if (tid < 32) {
            int w = wsum[tid];
            #pragma unroll
            for (int o = 1; o < 32; o <<= 1) {
                int nb = __shfl_up_sync(0xffffffffu, w, o);
                if (tid >= o) w += nb;
            }
            wsum[tid] = w;
        }
        __syncthreads();
        int excl = inc - v + ((tid >= 32) ? wsum[(tid >> 5) - 1] : 0) + s_carry;
        if (idx < n) {
            g_rowptr[idx] = excl;
            g_cnt[idx]    = 0;
            g_dis[idx]    = rsqrtf(g_deg[idx]);
        }
        __syncthreads();
        if (tid == 0) s_carry += wsum[31];
        __syncthreads();
    }
    if (tid == 0) g_rowptr[n] = e_;
}

__global__ void k_fill(const void* __restrict__ ei, const float* __restrict__ ew, int e_) {
    int e = blockIdx.x * blockDim.x + threadIdx.x;
    if (e >= e_) return;
    int s = edge_at(ei, e);
    int d = edge_at(ei, (long long)e_ + e);
    int p = g_rowptr[d] + atomicAdd(&g_cnt[d], 1);
    g_csr_src[p]  = s;
    g_csr_coef[p] = g_dis[s] * ew[e] * g_dis[d];
}

// ---------------- bf16 split kernels ----------------
__global__ void k_split_x(const float* __restrict__ src, long long total) {
    long long i = (long long)blockIdx.x * blockDim.x + threadIdx.x;
    if (i >= total) return;
    float v = src[i];
    __nv_bfloat16 h = __float2bfloat16(v);
    g_xh[i] = h;
    g_xl[i] = __float2bfloat16(v - __bfloat162float(h));
}
// W [K=1024, NO] row-major  ->  WT splits [NO, 1024] bf16
template <int WSEL>
__global__ void k_split_wt(const float* __restrict__ W, int NO) {
    int idx = blockIdx.x * blockDim.x + threadIdx.x;
    if (idx >= LM * NO) return;
    int k = idx / NO, nn = idx % NO;
    float v = W[idx];
    __nv_bfloat16 h = __float2bfloat16(v);
    __nv_bfloat16 l = __float2bfloat16(v - __bfloat162float(h));
    __nv_bfloat16* th = (WSEL == 1) ? g_wth : g_w1th;
    __nv_bfloat16* tl = (WSEL == 1) ? g_wtl : g_w1tl;
    th[(size_t)nn * LM + k] = h;
    tl[(size_t)nn * LM + k] = l;
}

// ---------------- mma.sync split-bf16 GEMM ----------------
// D[M, NG] = A[M,1024] @ B^T, A = Ah+Al, B = Bh+Bl, 3 tensor products, fp32 acc.
// Block 128x128, BK=32, 8 warps (warp tile 32x64), cp.async double buffer.
// EPI=1: v = d + bl + c*Wc + x*Wa, relu, store bf16 splits -> g_h1h/g_h1l (stride LM)
// EPI=0: store fp32 -> g_hp1 (stride HH)
template <int EPI, int ASEL, int BSEL>
__global__ __launch_bounds__(256)
void k_gemm_mma(int M,
                const float* __restrict__ cvec, const float* __restrict__ xvec,
                const float* __restrict__ Wc,   const float* __restrict__ Wa,
                const float* __restrict__ bl) {
    constexpr int BK = 32;
    constexpr int NIT = LM / BK;            // 32
    constexpr int STAGE = 32768;            // Ah 8K | Al 8K | Bh 8K | Bl 8K

    extern __shared__ char smem[];
    const uint32_t sbase0 = smem_to_u32(smem);

    const int tid    = threadIdx.x;
    const int lane   = tid & 31;
    const int wid    = tid >> 5;
    const int warp_m = wid & 3;             // 4 warps in M (32 rows each)
    const int warp_n = wid >> 2;            // 2 warps in N (64 cols each)

    const int block_row = blockIdx.y * 128;
    const int block_col = blockIdx.x * 128;

    const __nv_bfloat16* __restrict__ Ah = sel_a(ASEL, 0);
    const __nv_bfloat16* __restrict__ Al = sel_a(ASEL, 1);
    const __nv_bfloat16* __restrict__ Bh = sel_b(BSEL, 0);
    const __nv_bfloat16* __restrict__ Bl = sel_b(BSEL, 1);

    // per-thread load slots: idx -> (row = idx>>2, 16B chunk = idx&3)
    const int r0  = tid >> 2,            cb0 = tid & 3;
    const int r1  = (tid + 256) >> 2,    cb1 = tid & 3;     // (tid+256)&3 == tid&3
    const uint32_t so0 = (uint32_t)(r0 * 64 + ((cb0 ^ ((r0 >> 1) & 3)) * 16));
    const uint32_t so1 = (uint32_t)(r1 * 64 + ((cb1 ^ ((r1 >> 1) & 3)) * 16));

    auto issue_tile = [&](int stage, int k0) {
        uint32_t sb = sbase0 + stage * STAGE;
        // slot 0
        {
            long long arow = block_row + r0;
            size_t ga = (size_t)arow * LM + k0 + cb0 * 8;
            uint32_t asz = (arow < M) ? 16u : 0u;
            CP_ASYNC16(sb + so0,         (const char*)(Ah + ga), asz);
            CP_ASYNC16(sb + 8192 + so0,  (const char*)(Al + ga), asz);
            size_t gb = (size_t)(block_col + r0) * LM + k0 + cb0 * 8;
            CP_ASYNC16(sb + 16384 + so0, (const char*)(Bh + gb), 16u);
            CP_ASYNC16(sb + 24576 + so0, (const char*)(Bl + gb), 16u);
        }
        // slot 1
        {
            long long arow = block_row + r1;
            size_t ga = (size_t)arow * LM + k0 + cb1 * 8;
            uint32_t asz = (arow < M) ? 16u : 0u;
            CP_ASYNC16(sb + so1,         (const char*)(Ah + ga), asz);
            CP_ASYNC16(sb + 8192 + so1,  (const char*)(Al + ga), asz);
            size_t gb = (size_t)(block_col + r1) * LM + k0 + cb1 * 8;
            CP_ASYNC16(sb + 16384 + so1, (const char*)(Bh + gb), 16u);
            CP_ASYNC16(sb + 24576 + so1, (const char*)(Bl + gb), 16u);
        }
        CP_COMMIT();
    };

    float acc[2][8][4];
    #pragma unroll
    for (int i = 0; i < 2; i++)
        #pragma unroll
        for (int j = 0; j < 8; j++)
            #pragma unroll
            for (int q = 0; q < 4; q++) acc[i][j][q] = 0.0f;

    issue_tile(0, 0);

    for (int it = 0; it < NIT; it++) {
        if (it + 1 < NIT) {
            issue_tile((it + 1) & 1, (it + 1) * BK);
            CP_WAIT(1);
        } else {
            CP_WAIT(0);
        }
        __syncthreads();

        const uint32_t sb = sbase0 + (it & 1) * STAGE;
        #pragma unroll
        for (int ks = 0; ks < 2; ks++) {
            uint32_t aH[2][4], aL[2][4];
            #pragma unroll
            for (int mt = 0; mt < 2; mt++) {
                int row = warp_m * 32 + mt * 16 + (lane & 15);
                int cb  = ks * 2 + (lane >> 4);
                uint32_t off = (uint32_t)(row * 64 + ((cb ^ ((row >> 1) & 3)) * 16));
                LDSM_X4(aH[mt], sb + off);
                LDSM_X4(aL[mt], sb + 8192 + off);
            }
            #pragma unroll
            for (int g = 0; g < 4; g++) {
                uint32_t bh[4], blr[4];
                int row = warp_n * 64 + g * 16 + (lane & 15);
                int cb  = ks * 2 + (lane >> 4);
                uint32_t off = (uint32_t)(row * 64 + ((cb ^ ((row >> 1) & 3)) * 16));
                LDSM_X4(bh,  sb + 16384 + off);
                LDSM_X4(blr, sb + 24576 + off);
                #pragma unroll
                for (int mt = 0; mt < 2; mt++) {
                    #pragma unroll
                    for (int sub = 0; sub < 2; sub++) {
                        int nt = g * 2 + sub;
                        mma_bf16(acc[mt][nt], aH[mt], bh[sub],  bh[sub + 2]);   // hi*hi
                        mma_bf16(acc[mt][nt], aH[mt], blr[sub], blr[sub + 2]);  // hi*lo
                        mma_bf16(acc[mt][nt], aL[mt], bh[sub],  bh[sub + 2]);   // lo*hi
                    }
                }
            }
        }
        __syncthreads();
    }

    // ---------------- epilogue ----------------
    #pragma unroll
    for (int nt = 0; nt < 8; nt++) {
        int col = block_col + warp_n * 64 + nt * 8 + (lane & 3) * 2;
        float bl0 = 0.f, bl1 = 0.f, wc0 = 0.f, wc1 = 0.f, wa0 = 0.f, wa1 = 0.f;
        if (EPI == 1) {
            bl0 = bl[col];  bl1 = bl[col + 1];
            wc0 = Wc[col];  wc1 = Wc[col + 1];
            wa0 = Wa[col];  wa1 = Wa[col + 1];
        }
        #pragma unroll
        for (int mt = 0; mt < 2; mt++) {
            int rbase = block_row + warp_m * 32 + mt * 16 + (lane >> 2);
            #pragma unroll
            for (int h = 0; h < 2; h++) {
                int row = rbase + h * 8;
                if (row >= M) continue;
                float v0 = acc[mt][nt][h * 2 + 0];
                float v1 = acc[mt][nt][h * 2 + 1];
                if (EPI == 1) {
                    float cv = cvec[row], xv = xvec[row];
                    v0 = fmaxf(v0 + bl0 + cv * wc0 + xv * wa0, 0.f);
                    v1 = fmaxf(v1 + bl1 + cv * wc1 + xv * wa1, 0.f);
                    __nv_bfloat16 h0 = __float2bfloat16(v0);
                    __nv_bfloat16 h1 = __float2bfloat16(v1);
                    __nv_bfloat162 hh; hh.x = h0; hh.y = h1;
                    __nv_bfloat162 ll;
                    ll.x = __float2bfloat16(v0 - __bfloat162float(h0));
                    ll.y = __float2bfloat16(v1 - __bfloat162float(h1));
                    *(__nv_bfloat162*)&g_h1h[(size_t)row * LM + col] = hh;
                    *(__nv_bfloat162*)&g_h1l[(size_t)row * LM + col] = ll;
                } else {
                    float2 f2; f2.x = v0; f2.y = v1;
                    *(float2*)&g_hp1[(size_t)row * HH + col] = f2;
                }
            }
        }
    }
}

// ---------------- SIMT GEMM (small conv3 projection) ----------------
template <int BM, int BN, int BK, int TM, int TN, int ASEL, int DSEL>
__global__ __launch_bounds__((BM / TM) * (BN / TN))
void k_gemm(const float* __restrict__ Ap, const float* __restrict__ B,
            float* __restrict__ Cp, int M, int N, int K) {
    const float* __restrict__ A = sel_buf(ASEL, (float*)Ap);
    float* __restrict__ C = sel_buf(DSEL, Cp);

    constexpr int THREADS = (BM / TM) * (BN / TN);
    __shared__ float As[BK][BM];
    __shared__ float Bs[BK][BN];

    const int block_row = blockIdx.y * BM;
    const int block_col = blockIdx.x * BN;
    const int tid  = threadIdx.x;
    const int tcol = tid % (BN / TN);
    const int trow = tid / (BN / TN);

    float acc[TM][TN];
    #pragma unroll
    for (int i = 0; i < TM; i++)
        #pragma unroll
        for (int j = 0; j < TN; j++) acc[i][j] = 0.0f;

    for (int k0 = 0; k0 < K; k0 += BK) {
        #pragma unroll
        for (int i = tid; i < BM * BK / 4; i += THREADS) {
            int r  = i / (BK / 4);
            int c4 = i % (BK / 4);
            int grow = block_row + r;
            float4 v = (grow < M)
                ? *(const float4*)&A[(size_t)grow * K + k0 + c4 * 4]
                : make_float4(0.f, 0.f, 0.f, 0.f);
            As[c4 * 4 + 0][r] = v.x;
            As[c4 * 4 + 1][r] = v.y;
            As[c4 * 4 + 2][r] = v.z;
            As[c4 * 4 + 3][r] = v.w;
        }
        #pragma unroll
        for (int i = tid; i < BK * BN / 4; i += THREADS) {
            int r  = i / (BN / 4);
            int c4 = i % (BN / 4);
            *(float4*)&Bs[r][c4 * 4] =
                *(const float4*)&B[(size_t)(k0 + r) * N + block_col + c4 * 4];
        }
        __syncthreads();
        #pragma unroll
        for (int k = 0; k < BK; k++) {
            float a[TM], b[TN];
            #pragma unroll
            for (int i = 0; i < TM; i++) a[i] = As[k][trow * TM + i];
            #pragma unroll
            for (int j = 0; j < TN; j++) b[j] = Bs[k][tcol * TN + j];
            #pragma unroll
            for (int i = 0; i < TM; i++)
                #pragma unroll
                for (int j = 0; j < TN; j++)
                    acc[i][j] = fmaf(a[i], b[j], acc[i][j]);
        }
        __syncthreads();
    }
    #pragma unroll
    for (int i = 0; i < TM; i++) {
        int grow = block_row + trow * TM + i;
        if (grow >= M) continue;
        #pragma unroll
        for (int j = 0; j < TN; j++) {
            int gcol = block_col + tcol * TN + j;
            C[(size_t)grow * N + gcol] = acc[i][j];
        }
    }
}

// ---------------- GCN aggregation (CSR gather, warp per node) ----------------
template <int F, bool RELU, int HPSEL, int OSEL>
__global__ void k_agg(const float* __restrict__ bias, float* __restrict__ outp, int n) {
    const float* __restrict__ hp = sel_buf(HPSEL, nullptr);
    float* __restrict__ out = sel_buf(OSEL, outp);

    int warp = (blockIdx.x * blockDim.x + threadIdx.x) >> 5;
    int lane = threadIdx.x & 31;
    if (warp >= n) return;
    const int node = warp;
    constexpr int V = F / 32;
    float acc[V];

    float selfc = g_dis[node] * g_dis[node];
    const float* hrow = hp + (size_t)node * F + lane * V;
    #pragma unroll
    for (int j = 0; j < V; j++) acc[j] = selfc * hrow[j];

    int beg = g_rowptr[node];
    int end = g_rowptr[node + 1];
    for (int e = beg; e < end; e++) {
        int   s  = g_csr_src[e];
        float cf = g_csr_coef[e];
        const float* srow = hp + (size_t)s * F + lane * V;
        if (V == 4) {
            float4 v = *(const float4*)srow;
            acc[0] = fmaf(cf, v.x, acc[0]);
            acc[1] = fmaf(cf, v.y, acc[1]);
            acc[2] = fmaf(cf, v.z, acc[2]);
            acc[3] = fmaf(cf, v.w, acc[3]);
        } else {
            float2 v = *(const float2*)srow;
            acc[0] = fmaf(cf, v.x, acc[0]);
            acc[1] = fmaf(cf, v.y, acc[1]);
        }
    }
    #pragma unroll
    for (int j = 0; j < V; j++) {
        float v = acc[j] + bias[lane * V + j];
        if (RELU) v = fmaxf(v, 0.f);
        out[(size_t)node * F + lane * V + j] = v;
    }
}

// ---------------- launch ----------------
extern "C" void kernel_launch(void* const* d_in, const int* in_sizes, int n_in,
                              void* d_out, int out_size) {
    const float* x    = (const float*)d_in[0];
    const float* xout = (const float*)d_in[1];
    const float* c    = (const float*)d_in[2];
    const void*  ei   = d_in[3];
    const float* ew   = (const float*)d_in[4];
    const float* Wa   = (const float*)d_in[5];
    const float* Wc   = (const float*)d_in[6];
    const float* Wl   = (const float*)d_in[7];
    const float* bl   = (const float*)d_in[8];
    const float* W1   = (const float*)d_in[9];
    const float* b1   = (const float*)d_in[10];
    const float* W3   = (const float*)d_in[11];
    const float* b3   = (const float*)d_in[12];
    float* out = (float*)d_out;

    const int n = in_sizes[0];
    const int e = in_sizes[3] / 2;

    const int SMEM_MMA = 2 * 32768;   // 64 KB dynamic
    cudaFuncSetAttribute(k_gemm_mma<1, 1, 1>,
                         cudaFuncAttributeMaxDynamicSharedMemorySize, SMEM_MMA);
    cudaFuncSetAttribute(k_gemm_mma<0, 2, 2>,
                         cudaFuncAttributeMaxDynamicSharedMemorySize, SMEM_MMA);

    // --- dtype detection + graph preprocessing ---
    k_detect<<<1, 32>>>((const unsigned int*)ei);
    k_init  <<<(n + 255) / 256, 256>>>(n);
    k_count <<<(e + 255) / 256, 256>>>(ei, ew, e);
    k_scan  <<<1, 1024>>>(n, e);
    k_fill  <<<(e + 255) / 256, 256>>>(ei, ew, e);

    // --- bf16 splits: xout, Wl^T, W1^T ---
    {
        long long tot = (long long)n * LM;
        k_split_x<<<(unsigned)((tot + 511) / 512), 512>>>(xout, tot);
        k_split_wt<1><<<(LM * LM + 255) / 256, 256>>>(Wl, LM);
        k_split_wt<2><<<(LM * HH + 255) / 256, 256>>>(W1, HH);
    }

    // --- layer 0 (mma.sync): h1 splits = relu(xout @ Wl + bl + c*Wc + x*Wa) ---
    {
        dim3 grid(LM / 128, (n + 127) / 128);
        k_gemm_mma<1, 1, 1><<<grid, 256, SMEM_MMA>>>(n, c, x, Wc, Wa, bl);
    }
    // --- conv1 projection (mma.sync): g_hp1 = h1 @ W1 ---
    {
        dim3 grid(HH / 128, (n + 127) / 128);
        k_gemm_mma<0, 2, 2><<<grid, 256, SMEM_MMA>>>(n, nullptr, nullptr, nullptr, nullptr, nullptr);
    }
    // --- conv1 aggregation + bias + relu: g_h2 ---
    k_agg<HH, true, 2, 3><<<(n * 32 + 255) / 256, 256>>>(b1, nullptr, n);

    // --- conv3 projection (SIMT): g_hp3 = g_h2 @ W3 ---
    {
        dim3 grid(OUTC / 64, (n + 127) / 128);
        k_gemm<128, 64, 16, 8, 4, 3, 4><<<grid, 256>>>(nullptr, W3, nullptr, n, OUTC, HH);
    }
    // --- conv3 aggregation + bias: out ---
    k_agg<OUTC, false, 4, 0><<<(n * 32 + 255) / 256, 256>>>(b3, out, n);
}